// round 8
// baseline (speedup 1.0000x reference)
#include <cuda_runtime.h>
#include <cuda_bf16.h>
#include <math.h>
#include <stdint.h>

// Problem constants (fixed for this instance)
#define HID   512
#define NH    8
#define HD    64
#define BQ    2048   // query length
#define BB    2      // batch
#define SSQ   4096   // side length
#define TOPK  64
#define NEGV  (-1e9f)

// -------- scratch (device globals; no allocation) --------
__device__ float g_q[(size_t)BB * BQ * HID];     // 8 MB
__device__ float g_k[(size_t)SSQ * HID];         // 8 MB
__device__ float g_v[(size_t)SSQ * HID];         // 8 MB
__device__ float g_ctx[(size_t)BB * BQ * HID];   // 8 MB
__device__ float g_scores[(size_t)BB * NH * BQ * SSQ];  // 512 MB
// bf16 2-way splits of q and k (hi / mid)
__device__ __nv_bfloat16 g_qh[(size_t)BB * BQ * HID];
__device__ __nv_bfloat16 g_qm[(size_t)BB * BQ * HID];
__device__ __nv_bfloat16 g_kh[(size_t)SSQ * HID];
__device__ __nv_bfloat16 g_km[(size_t)SSQ * HID];

// ============================================================
// bf16 MMA (baseline PTX, sm_80+): D += A*B, m16n8k16, fp32 accum
// ============================================================
__device__ __forceinline__ void mma_bf16(float c[4],
                                         const uint32_t a[4],
                                         const uint32_t b[2]) {
    asm volatile(
        "mma.sync.aligned.m16n8k16.row.col.f32.bf16.bf16.f32 "
        "{%0,%1,%2,%3}, {%4,%5,%6,%7}, {%8,%9}, {%0,%1,%2,%3};"
        : "+f"(c[0]), "+f"(c[1]), "+f"(c[2]), "+f"(c[3])
        : "r"(a[0]), "r"(a[1]), "r"(a[2]), "r"(a[3]),
          "r"(b[0]), "r"(b[1]));
}

// ============================================================
// Generic SGEMM: C[M,512] = A[M,512] @ W[512,512] + bias
// (known-good SIMT version; projections)
// ============================================================
__global__ void __launch_bounds__(256) sgemm_bias(
    const float* __restrict__ A, const float* __restrict__ W,
    const float* __restrict__ bias, float* __restrict__ C)
{
    __shared__ float As[16][132];
    __shared__ float Ws[16][132];

    const int tid = threadIdx.x;
    const int bm = blockIdx.y * 128;
    const int bn = blockIdx.x * 128;
    const int tm = tid >> 4;
    const int tn = tid & 15;

    float acc[8][8];
#pragma unroll
    for (int i = 0; i < 8; i++)
#pragma unroll
        for (int j = 0; j < 8; j++) acc[i][j] = 0.f;

    for (int k0 = 0; k0 < 512; k0 += 16) {
#pragma unroll
        for (int it = 0; it < 2; it++) {
            int l = tid + it * 256;
            int r = l >> 2;
            int c4 = (l & 3) * 4;
            float4 av = *(const float4*)(A + (size_t)(bm + r) * 512 + k0 + c4);
            As[c4 + 0][r] = av.x;
            As[c4 + 1][r] = av.y;
            As[c4 + 2][r] = av.z;
            As[c4 + 3][r] = av.w;
        }
#pragma unroll
        for (int it = 0; it < 2; it++) {
            int l = tid + it * 256;
            int kr = l >> 5;
            int c4 = (l & 31) * 4;
            *(float4*)&Ws[kr][c4] =
                *(const float4*)(W + (size_t)(k0 + kr) * 512 + bn + c4);
        }
        __syncthreads();

#pragma unroll
        for (int k = 0; k < 16; k++) {
            float ra[8], rb[8];
            *(float4*)&ra[0] = *(float4*)&As[k][tm * 4];
            *(float4*)&ra[4] = *(float4*)&As[k][64 + tm * 4];
            *(float4*)&rb[0] = *(float4*)&Ws[k][tn * 4];
            *(float4*)&rb[4] = *(float4*)&Ws[k][64 + tn * 4];
#pragma unroll
            for (int i = 0; i < 8; i++)
#pragma unroll
                for (int j = 0; j < 8; j++)
                    acc[i][j] = fmaf(ra[i], rb[j], acc[i][j]);
        }
        __syncthreads();
    }

#pragma unroll
    for (int i = 0; i < 8; i++) {
        int r = bm + ((i < 4) ? (tm * 4 + i) : (64 + tm * 4 + (i - 4)));
#pragma unroll
        for (int jj = 0; jj < 2; jj++) {
            int c = bn + jj * 64 + tn * 4;
            float4 o;
            o.x = acc[i][jj * 4 + 0] + bias[c + 0];
            o.y = acc[i][jj * 4 + 1] + bias[c + 1];
            o.z = acc[i][jj * 4 + 2] + bias[c + 2];
            o.w = acc[i][jj * 4 + 3] + bias[c + 3];
            *(float4*)(C + (size_t)r * 512 + c) = o;
        }
    }
}

// ============================================================
// fp32 -> bf16 2-way split: h=bf16(x), m=bf16(x-h)
// ============================================================
__global__ void __launch_bounds__(256) split2_kernel(
    const float* __restrict__ src,
    __nv_bfloat16* __restrict__ oh,
    __nv_bfloat16* __restrict__ om, int n4)
{
    int i = blockIdx.x * 256 + threadIdx.x;
    if (i >= n4) return;
    float4 x = ((const float4*)src)[i];
    float vs[4] = {x.x, x.y, x.z, x.w};
    __nv_bfloat16 h[4], m[4];
#pragma unroll
    for (int j = 0; j < 4; j++) {
        float v = vs[j];
        __nv_bfloat16 a = __float2bfloat16(v);
        float r1 = v - __bfloat162float(a);
        __nv_bfloat16 b = __float2bfloat16(r1);
        h[j] = a; m[j] = b;
    }
    ((__nv_bfloat162*)oh)[i * 2 + 0] = __nv_bfloat162(h[0], h[1]);
    ((__nv_bfloat162*)oh)[i * 2 + 1] = __nv_bfloat162(h[2], h[3]);
    ((__nv_bfloat162*)om)[i * 2 + 0] = __nv_bfloat162(m[0], m[1]);
    ((__nv_bfloat162*)om)[i * 2 + 1] = __nv_bfloat162(m[2], m[3]);
}

// ============================================================
// Scores via mma.sync bf16 (4-term split (h+m)x(h+m)):
//   D[128q,128s] = Q K^T;  scores = D*0.125 + (mask?0:-1e9)
// grid (BB*NH, BQ/128), 256 threads (8 warps = 2m x 4n), 2 CTA/SM
// smem: 4 tiles (Qh,Qm,Kh,Km), each 128 rows x 72 bf16 = 18,432 B
// ============================================================
#define TW         36                    // uint32 words per smem row
#define TILE_WORDS (128 * TW)            // 4608 words = 18,432 B
#define SCORES_SMEM (4 * TILE_WORDS * 4) // 73,728 B

__global__ void __launch_bounds__(256, 2) scores_mma(const int* __restrict__ mask)
{
    extern __shared__ uint32_t sm32[];
    uint32_t* Qt[2] = { sm32, sm32 + TILE_WORDS };
    uint32_t* Kt[2] = { sm32 + 2 * TILE_WORDS, sm32 + 3 * TILE_WORDS };

    const int tid = threadIdx.x;
    const int wid = tid >> 5;
    const int lid = tid & 31;
    const int g   = lid >> 2;      // groupID 0..7
    const int tig = lid & 3;       // thread-in-group 0..3
    const int wm  = wid & 1;       // 2 m-groups of 64 rows
    const int wn  = wid >> 1;      // 4 n-groups of 32 cols

    const int bh = blockIdx.x;     // 0..15
    const int b  = bh >> 3;
    const int h  = bh & 7;
    const int q0 = blockIdx.y * 128;

    // ---- load Q tiles (hi/mid), resident for all s-tiles
    {
        const size_t qoff = ((size_t)(b * BQ + q0)) * 512 + h * 64;
        const uint4* src[2] = { (const uint4*)(g_qh + qoff),
                                (const uint4*)(g_qm + qoff) };
#pragma unroll
        for (int s = 0; s < 2; s++) {
            uint4* dst = (uint4*)Qt[s];
#pragma unroll
            for (int it = 0; it < 4; it++) {
                int t = tid + it * 256;      // 0..1023
                int r = t >> 3;              // 0..127
                int c = t & 7;               // 0..7
                dst[r * 9 + c] = src[s][(size_t)r * 64 + c];
            }
        }
    }

    float* srow0 = g_scores + ((size_t)bh * BQ + q0) * SSQ;
    const int* mrow0 = mask + ((size_t)b * BQ + q0) * SSQ;

    for (int st = 0; st < SSQ / 128; st++) {
        const int s0 = st * 128;

        __syncthreads();   // prev-iter fragment reads done before overwrite
        {
            const size_t koff = (size_t)s0 * 512 + h * 64;
            const uint4* src[2] = { (const uint4*)(g_kh + koff),
                                    (const uint4*)(g_km + koff) };
#pragma unroll
            for (int s = 0; s < 2; s++) {
                uint4* dst = (uint4*)Kt[s];
#pragma unroll
                for (int it = 0; it < 4; it++) {
                    int t = tid + it * 256;
                    int r = t >> 3;
                    int c = t & 7;
                    dst[r * 9 + c] = src[s][(size_t)r * 64 + c];
                }
            }
        }
        __syncthreads();

        float acc[4][4][4];
#pragma unroll
        for (int mt = 0; mt < 4; mt++)
#pragma unroll
            for (int nt = 0; nt < 4; nt++)
#pragma unroll
                for (int e = 0; e < 4; e++) acc[mt][nt][e] = 0.f;

        // 4 k-chunks of 16
#pragma unroll
        for (int kc = 0; kc < 4; kc++) {
            const int kw = kc * 8;   // word offset within row

            uint32_t bh_[4][2], bm_[4][2];
#pragma unroll
            for (int nt = 0; nt < 4; nt++) {
                const int nr = (wn * 32 + nt * 8 + g) * TW + kw + tig;
                bh_[nt][0] = Kt[0][nr];     bh_[nt][1] = Kt[0][nr + 4];
                bm_[nt][0] = Kt[1][nr];     bm_[nt][1] = Kt[1][nr + 4];
            }

#pragma unroll
            for (int mt = 0; mt < 4; mt++) {
                const int r0 = (wm * 64 + mt * 16 + g) * TW + kw + tig;
                const int r8 = r0 + 8 * TW;
                uint32_t ah_[4], am_[4];
                ah_[0] = Qt[0][r0]; ah_[1] = Qt[0][r8];
                ah_[2] = Qt[0][r0 + 4]; ah_[3] = Qt[0][r8 + 4];
                am_[0] = Qt[1][r0]; am_[1] = Qt[1][r8];
                am_[2] = Qt[1][r0 + 4]; am_[3] = Qt[1][r8 + 4];

                // 4 terms x 4 nt; nt-inner for ILP across accumulators
#pragma unroll
                for (int nt = 0; nt < 4; nt++) mma_bf16(acc[mt][nt], ah_, bh_[nt]);
#pragma unroll
                for (int nt = 0; nt < 4; nt++) mma_bf16(acc[mt][nt], ah_, bm_[nt]);
#pragma unroll
                for (int nt = 0; nt < 4; nt++) mma_bf16(acc[mt][nt], am_, bh_[nt]);
#pragma unroll
                for (int nt = 0; nt < 4; nt++) mma_bf16(acc[mt][nt], am_, bm_[nt]);
            }
        }

        // ---- epilogue: scale + mask + store (direct from C fragments)
#pragma unroll
        for (int mt = 0; mt < 4; mt++) {
            const int qr0 = wm * 64 + mt * 16 + g;
#pragma unroll
            for (int nt = 0; nt < 4; nt++) {
                const int col = s0 + wn * 32 + nt * 8 + tig * 2;
                {
                    const size_t off = (size_t)qr0 * SSQ + col;
                    int2 m2 = *(const int2*)(mrow0 + off);
                    float2 v;
                    v.x = acc[mt][nt][0] * 0.125f + (m2.x ? 0.f : NEGV);
                    v.y = acc[mt][nt][1] * 0.125f + (m2.y ? 0.f : NEGV);
                    *(float2*)(srow0 + off) = v;
                }
                {
                    const size_t off = (size_t)(qr0 + 8) * SSQ + col;
                    int2 m2 = *(const int2*)(mrow0 + off);
                    float2 v;
                    v.x = acc[mt][nt][2] * 0.125f + (m2.x ? 0.f : NEGV);
                    v.y = acc[mt][nt][3] * 0.125f + (m2.y ? 0.f : NEGV);
                    *(float2*)(srow0 + off) = v;
                }
            }
        }
    }
}

// ============================================================
// Top-k: radix select on MMA scores + EXACT fp32 re-ranking of
// boundary-ambiguous candidates (sequential-k fmaf, matching the
// R3 kernel that passed), then softmax + ctx gather.
// ============================================================
#define AMB_EPS 2e-4f
#define AMB_CAP 128

__global__ void __launch_bounds__(256) topk_ctx_kernel()
{
    const size_t row = blockIdx.x;
    const int q = (int)(row & 2047);
    const int bh = (int)(row >> 11);
    const int h = bh & 7;
    const int b = bh >> 3;

    const float* srow = g_scores + row * SSQ;
    const int tid = threadIdx.x;

    __shared__ float red[256];
    __shared__ unsigned hist[256];
    __shared__ unsigned scan[256];
    __shared__ unsigned sh_prefix, sh_want;
    __shared__ int cnt;
    __shared__ int nB;
    __shared__ int sidx[512];
    __shared__ float sp[512];
    __shared__ float ctxs[4][64];
    __shared__ float qv[64];
    __shared__ int   Bidx[AMB_CAP];
    __shared__ float Bex[AMB_CAP];

    // preload exact q row (fp32)
    if (tid < 64)
        qv[tid] = g_q[((size_t)(b * BQ + q)) * 512 + h * HD + tid];

    // ---- load row, compute sortable keys + local max ----
    float val[16];
    unsigned u[16];
    float lmax = -INFINITY;
#pragma unroll
    for (int i = 0; i < 16; i++) {
        float x = srow[tid + i * 256];
        val[i] = x;
        unsigned bits = __float_as_uint(x);
        u[i] = (bits & 0x80000000u) ? ~bits : (bits | 0x80000000u);
        lmax = fmaxf(lmax, x);
    }

    red[tid] = lmax;
    __syncthreads();
    for (int o = 128; o > 0; o >>= 1) {
        if (tid < o) red[tid] = fmaxf(red[tid], red[tid + o]);
        __syncthreads();
    }
    const float rowmax = red[0];
    __syncthreads();

    if (tid == 0) { sh_prefix = 0u; sh_want = TOPK; cnt = 0; nB = 0; }
    unsigned maskbits = 0u;
    __syncthreads();

    // ---- radix select: 64th largest key (on MMA scores) ----
    for (int pass = 0; pass < 4; pass++) {
        const int shift = 24 - 8 * pass;
        hist[tid] = 0u;
        __syncthreads();
        const unsigned prefix = sh_prefix;
#pragma unroll
        for (int i = 0; i < 16; i++)
            if ((u[i] & maskbits) == prefix)
                atomicAdd(&hist[(u[i] >> shift) & 255u], 1u);
        __syncthreads();

        scan[tid] = hist[255 - tid];
        __syncthreads();
        for (int o = 1; o < 256; o <<= 1) {
            unsigned add = (tid >= o) ? scan[tid - o] : 0u;
            __syncthreads();
            scan[tid] += add;
            __syncthreads();
        }
        const unsigned want = sh_want;
        const unsigned cum = scan[tid];
        const unsigned prev = (tid == 0) ? 0u : scan[tid - 1];
        __syncthreads();
        if (cum >= want && prev < want) {
            sh_prefix = prefix | ((255u - (unsigned)tid) << shift);
            sh_want = want - prev;
        }
        maskbits |= (0xFFu << shift);
        __syncthreads();
    }

    // decode threshold key -> float
    float thresh_f;
    {
        unsigned k = sh_prefix;
        unsigned bits = (k & 0x80000000u) ? (k & 0x7FFFFFFFu) : ~k;
        thresh_f = __uint_as_float(bits);
    }

    // ---- classify: definite-in / ambiguous / out ----
    float lsum = 0.f;
#pragma unroll
    for (int i = 0; i < 16; i++) {
        float s = val[i];
        if (s > thresh_f + AMB_EPS) {
            float p = expf(s - rowmax);
            lsum += p;
            int pos = atomicAdd(&cnt, 1);
            if (pos < 512) { sidx[pos] = tid + i * 256; sp[pos] = p; }
        } else if (s >= thresh_f - AMB_EPS) {
            int pos = atomicAdd(&nB, 1);
            if (pos < AMB_CAP) Bidx[pos] = tid + i * 256;
        }
    }
    __syncthreads();
    const int nd = cnt;                      // definite count (<= 63)
    const int nb = (nB < AMB_CAP) ? nB : AMB_CAP;

    // ---- exact fp32 recompute of ambiguous scores (sequential k) ----
    if (tid < nb) {
        const float* kr = g_k + (size_t)Bidx[tid] * 512 + h * HD;
        float a = 0.f;
#pragma unroll
        for (int d = 0; d < 64; d++) a = fmaf(qv[d], kr[d], a);
        Bex[tid] = a * 0.125f;
    }
    __syncthreads();

    // ---- rank ambiguous by exact score; keep if nd + (#greater) < 64 ----
    if (tid < nb) {
        const float s = Bex[tid];
        int greater = 0;
        for (int j = 0; j < nb; j++) greater += (Bex[j] > s) ? 1 : 0;
        if (nd + greater < TOPK) {
            float p = expf(s - rowmax);
            lsum += p;
            int pos = atomicAdd(&cnt, 1);
            if (pos < 512) { sidx[pos] = Bidx[tid]; sp[pos] = p; }
        }
    }

    // ---- sum reduction ----
    red[tid] = lsum;
    __syncthreads();
    for (int o = 128; o > 0; o >>= 1) {
        if (tid < o) red[tid] += red[tid + o];
        __syncthreads();
    }
    const float invd = 1.0f / red[0];

    // ---- ctx = sum_sel p * v[s, h, :] ----
    const int g = tid >> 6;
    const int d = tid & 63;
    ctxs[g][d] = 0.f;
    __syncthreads();
    const int n = (cnt < 512) ? cnt : 512;
    const float* vh = g_v + h * HD;
    float a = 0.f;
    for (int e = g; e < n; e += 4)
        a += sp[e] * vh[(size_t)sidx[e] * 512 + d];
    ctxs[g][d] = a;
    __syncthreads();

    if (tid < 64) {
        float r2 = (ctxs[0][tid] + ctxs[1][tid] + ctxs[2][tid] + ctxs[3][tid]) * invd;
        g_ctx[((size_t)(b * BQ + q)) * 512 + h * HD + tid] = r2;
    }
}

// ============================================================
// host launcher
// ============================================================
extern "C" void kernel_launch(void* const* d_in, const int* in_sizes, int n_in,
                              void* d_out, int out_size)
{
    const float* main_in = (const float*)d_in[0];
    const float* side_in = (const float*)d_in[1];
    const int*   mask    = (const int*)d_in[2];
    const float* Wq = (const float*)d_in[3];
    const float* bq = (const float*)d_in[4];
    const float* Wk = (const float*)d_in[5];
    const float* bk = (const float*)d_in[6];
    const float* Wv = (const float*)d_in[7];
    const float* bv = (const float*)d_in[8];
    const float* Wo = (const float*)d_in[9];
    const float* bo = (const float*)d_in[10];
    float* out = (float*)d_out;

    float *pq, *pk, *pv, *pctx;
    cudaGetSymbolAddress((void**)&pq, g_q);
    cudaGetSymbolAddress((void**)&pk, g_k);
    cudaGetSymbolAddress((void**)&pv, g_v);
    cudaGetSymbolAddress((void**)&pctx, g_ctx);
    __nv_bfloat16 *pqh, *pqm, *pkh, *pkm;
    cudaGetSymbolAddress((void**)&pqh, g_qh);
    cudaGetSymbolAddress((void**)&pqm, g_qm);
    cudaGetSymbolAddress((void**)&pkh, g_kh);
    cudaGetSymbolAddress((void**)&pkm, g_km);

    cudaFuncSetAttribute(scores_mma, cudaFuncAttributeMaxDynamicSharedMemorySize,
                         SCORES_SMEM);

    dim3 gB(512 / 128, (BB * BQ) / 128);   // (4, 32)

    // projections (q,k,v) — fp32 SIMT (q,k must stay fp32-exact)
    sgemm_bias<<<gB, 256>>>(main_in, Wq, bq, pq);
    sgemm_bias<<<gB, 256>>>(side_in, Wk, bk, pk);
    sgemm_bias<<<gB, 256>>>(side_in, Wv, bv, pv);

    // bf16 2-way splits of q and k
    {
        int n4q = (BB * BQ * HID) / 4;   // 524288
        int n4k = (SSQ * HID) / 4;       // 524288
        split2_kernel<<<(n4q + 255) / 256, 256>>>(pq, pqh, pqm, n4q);
        split2_kernel<<<(n4k + 255) / 256, 256>>>(pk, pkh, pkm, n4k);
    }

    // masked scaled scores via tensor cores (bf16 4-term)
    scores_mma<<<dim3(BB * NH, BQ / 128), 256, SCORES_SMEM>>>(mask);

    // top-64 with exact boundary resolution + softmax + ctx gather
    topk_ctx_kernel<<<BB * NH * BQ, 256>>>();

    // output projection
    sgemm_bias<<<gB, 256>>>(pctx, Wo, bo, out);
}